// round 1
// baseline (speedup 1.0000x reference)
#include <cuda_runtime.h>

// UnPooling (max-unpool 2x2, stride 2):
// x:      [16, 128, 128, 256] f32
// pooled: [16,  64,  64, 256] f32
// out:    [16, 128, 128, 256] f32
// out[n, 2hp+dh*, 2wp+dw*, c] = max(pooled[n,hp,wp,c], 0) where (dh*,dw*) is
// the first-max argmax of the 2x2 window of x; all other slots are 0.

static constexpr int N_  = 16;
static constexpr int H_  = 128;
static constexpr int W_  = 128;
static constexpr int C_  = 256;
static constexpr int HP_ = H_ / 2;
static constexpr int WP_ = W_ / 2;
static constexpr int C4_ = C_ / 4;            // 64 float4 per channel row
static constexpr int ROW4_ = W_ * C4_;        // x row stride in float4 units (8192)
static constexpr int TOTAL4 = N_ * HP_ * WP_ * C4_;  // pooled float4 count = 4,194,304

__global__ __launch_bounds__(256)
void unpool_kernel(const float4* __restrict__ x,
                   const float4* __restrict__ pooled,
                   float4* __restrict__ out)
{
    int i = blockIdx.x * blockDim.x + threadIdx.x;
    if (i >= TOTAL4) return;

    // Decompose pooled float4 index: ((n*HP + hp)*WP + wp)*C4 + c4
    int c4 = i & (C4_ - 1);
    int t  = i >> 6;            // / C4_
    int wp = t & (WP_ - 1);
    t >>= 6;                    // / WP_
    int hp = t & (HP_ - 1);
    int n  = t >> 6;            // / HP_

    // Base index into x/out (float4 units) at (n, 2hp, 2wp, c4)
    int base = ((n * H_ + 2 * hp) * W_ + 2 * wp) * C4_ + c4;

    float4 v00 = x[base];
    float4 v01 = x[base + C4_];
    float4 v10 = x[base + ROW4_];
    float4 v11 = x[base + ROW4_ + C4_];
    float4 pv  = pooled[i];

    float a0[4] = {v00.x, v00.y, v00.z, v00.w};
    float a1[4] = {v01.x, v01.y, v01.z, v01.w};
    float a2[4] = {v10.x, v10.y, v10.z, v10.w};
    float a3[4] = {v11.x, v11.y, v11.z, v11.w};
    float p4[4] = {pv.x, pv.y, pv.z, pv.w};

    float o0[4], o1[4], o2[4], o3[4];

    #pragma unroll
    for (int l = 0; l < 4; ++l) {
        float best = a0[l];
        int bi = 0;
        if (a1[l] > best) { best = a1[l]; bi = 1; }
        if (a2[l] > best) { best = a2[l]; bi = 2; }
        if (a3[l] > best) {              bi = 3; }
        float val = fmaxf(p4[l], 0.0f);
        o0[l] = (bi == 0) ? val : 0.0f;
        o1[l] = (bi == 1) ? val : 0.0f;
        o2[l] = (bi == 2) ? val : 0.0f;
        o3[l] = (bi == 3) ? val : 0.0f;
    }

    out[base]               = make_float4(o0[0], o0[1], o0[2], o0[3]);
    out[base + C4_]         = make_float4(o1[0], o1[1], o1[2], o1[3]);
    out[base + ROW4_]       = make_float4(o2[0], o2[1], o2[2], o2[3]);
    out[base + ROW4_ + C4_] = make_float4(o3[0], o3[1], o3[2], o3[3]);
}

extern "C" void kernel_launch(void* const* d_in, const int* in_sizes, int n_in,
                              void* d_out, int out_size)
{
    const float4* x      = (const float4*)d_in[0];
    const float4* pooled = (const float4*)d_in[1];
    float4* out          = (float4*)d_out;

    const int threads = 256;
    const int blocks  = (TOTAL4 + threads - 1) / threads;
    unpool_kernel<<<blocks, threads>>>(x, pooled, out);
}